// round 12
// baseline (speedup 1.0000x reference)
#include <cuda_runtime.h>
#include <cuda_bf16.h>
#include <stdint.h>
#include <math.h>

#define BATCH 65536
#define DIN 256
#define DH 512
#define DOUT 128

// ---------------- scratch (__device__ globals; no cudaMalloc allowed) ----------------
__device__ __nv_bfloat16 g_xhi[(size_t)BATCH * DIN];
__device__ __nv_bfloat16 g_xlo[(size_t)BATCH * DIN];
__device__ __nv_bfloat16 g_w1hi[DH * DIN], g_w1lo[DH * DIN];
__device__ __nv_bfloat16 g_w2hi[DOUT * DH], g_w2lo[DOUT * DH];
__device__ __nv_bfloat16 g_hhi[(size_t)BATCH * DH];
__device__ __nv_bfloat16 g_hlo[(size_t)BATCH * DH];
__device__ float g_c[(size_t)BATCH * DH];          // fp32 GEMM output (reused by both layers)
__device__ float g_xn2[BATCH], g_hn2[BATCH];

__device__ __forceinline__ float artanh_fast(float z) {
    z = fminf(fmaxf(z, -1.0f + 1e-7f), 1.0f - 1e-7f);
    return 0.5f * __logf((1.0f + z) / (1.0f - z));
}
__device__ __forceinline__ float tanh_fast(float x) {
    float ax = fabsf(x);
    float t = __expf(-2.0f * ax);
    float r = (1.0f - t) / (1.0f + t);
    return copysignf(r, x);
}
__device__ __forceinline__ float wred(float v) {
    #pragma unroll
    for (int o = 16; o > 0; o >>= 1) v += __shfl_xor_sync(0xffffffffu, v, o);
    return v;
}
__device__ __forceinline__ uint32_t smem_u32(const void* p) {
    uint32_t a;
    asm("{ .reg .u64 t; cvta.to.shared.u64 t, %1; cvt.u32.u64 %0, t; }" : "=r"(a) : "l"(p));
    return a;
}

#define LDSM4(r0, r1, r2, r3, addr)                                               \
    asm volatile("ldmatrix.sync.aligned.m8n8.x4.shared.b16 {%0,%1,%2,%3}, [%4];"  \
                 : "=r"(r0), "=r"(r1), "=r"(r2), "=r"(r3) : "r"(addr))

#define MMA16816(c, a, b)                                                          \
    asm volatile("mma.sync.aligned.m16n8k16.row.col.f32.bf16.bf16.f32 "            \
                 "{%0,%1,%2,%3}, {%4,%5,%6,%7}, {%8,%9}, {%0,%1,%2,%3};"           \
                 : "+f"((c)[0]), "+f"((c)[1]), "+f"((c)[2]), "+f"((c)[3])          \
                 : "r"((a)[0]), "r"((a)[1]), "r"((a)[2]), "r"((a)[3]),             \
                   "r"((b)[0]), "r"((b)[1]))

#define CP16(dst, src)                                                             \
    asm volatile("cp.async.cg.shared.global [%0], [%1], 16;" :: "r"(dst), "l"(src))
#define CP_COMMIT() asm volatile("cp.async.commit_group;" ::: "memory")
#define CP_WAIT(n)  asm volatile("cp.async.wait_group %0;" :: "n"(n) : "memory")

// ---------------- conversion kernels ----------------
__global__ void __launch_bounds__(256) convert_x_kernel(const float* __restrict__ x) {
    int gw = (blockIdx.x * 256 + threadIdx.x) >> 5;   // row
    int lane = threadIdx.x & 31;
    const float4* xr = reinterpret_cast<const float4*>(x + (size_t)gw * DIN);
    float s2 = 0.f;
    #pragma unroll
    for (int i = 0; i < 2; i++) {
        int q = lane + 32 * i;
        float4 v = xr[q];
        s2 += v.x * v.x + v.y * v.y + v.z * v.z + v.w * v.w;
        __nv_bfloat16 h0 = __float2bfloat16(v.x), h1 = __float2bfloat16(v.y);
        __nv_bfloat16 h2 = __float2bfloat16(v.z), h3 = __float2bfloat16(v.w);
        __nv_bfloat16 l0 = __float2bfloat16(v.x - __bfloat162float(h0));
        __nv_bfloat16 l1 = __float2bfloat16(v.y - __bfloat162float(h1));
        __nv_bfloat16 l2 = __float2bfloat16(v.z - __bfloat162float(h2));
        __nv_bfloat16 l3 = __float2bfloat16(v.w - __bfloat162float(h3));
        __nv_bfloat162* dh = reinterpret_cast<__nv_bfloat162*>(g_xhi) + ((size_t)gw * DIN >> 1) + q * 2;
        __nv_bfloat162* dl = reinterpret_cast<__nv_bfloat162*>(g_xlo) + ((size_t)gw * DIN >> 1) + q * 2;
        __nv_bfloat162 th; th.x = h0; th.y = h1; dh[0] = th;
        th.x = h2; th.y = h3; dh[1] = th;
        __nv_bfloat162 tl; tl.x = l0; tl.y = l1; dl[0] = tl;
        tl.x = l2; tl.y = l3; dl[1] = tl;
    }
    s2 = wred(s2);
    if (lane == 0) g_xn2[gw] = s2;
}

__global__ void __launch_bounds__(256) convert_w_kernel(const float* __restrict__ W1,
                                                        const float* __restrict__ W2) {
    int i = blockIdx.x * 256 + threadIdx.x;
    if (i < DH * DIN) {
        float v = W1[i];
        __nv_bfloat16 h = __float2bfloat16(v);
        g_w1hi[i] = h;
        g_w1lo[i] = __float2bfloat16(v - __bfloat162float(h));
    }
    if (i < DOUT * DH) {
        float v = W2[i];
        __nv_bfloat16 h = __float2bfloat16(v);
        g_w2hi[i] = h;
        g_w2lo[i] = __float2bfloat16(v - __bfloat162float(h));
    }
}

// ---------------- mma.sync split-bf16 GEMM, 3-stage cp.async ring ----------------
// BM=128, BN=128, BK=32. 256 threads = 8 warps (2 in M x 4 in N), warp tile 64x32.
#define LDSP 40
#define SPLIT_TILE (128 * LDSP)                   // elements per split tile (A or B)
#define STAGE_ELEMS (4 * SPLIT_TILE)              // Ahi | Alo | Bhi | Blo
#define NSTAGE 3
#define GEMM_SMEM (NSTAGE * STAGE_ELEMS * 2)      // bytes

template<int K, int N>
__global__ void __launch_bounds__(256, 1) mma_gemm(const __nv_bfloat16* __restrict__ Ahi,
                                                   const __nv_bfloat16* __restrict__ Alo,
                                                   const __nv_bfloat16* __restrict__ Bhi,
                                                   const __nv_bfloat16* __restrict__ Blo,
                                                   float* __restrict__ C)
{
    extern __shared__ __nv_bfloat16 smem[];
    const int tid = threadIdx.x, lane = tid & 31, wid = tid >> 5;
    const int warpM = wid >> 2, warpN = wid & 3;        // 2 x 4
    const int bm = blockIdx.y * 128, bn = blockIdx.x * 128;
    const uint32_t sbase = smem_u32(smem);

    float acc[4][4][4];
    #pragma unroll
    for (int i = 0; i < 4; i++)
        #pragma unroll
        for (int j = 0; j < 4; j++)
            #pragma unroll
            for (int l = 0; l < 4; l++) acc[i][j][l] = 0.f;

    // cp.async addressing: each tile is 128 rows x 32 cols = 512 uint4, 2 per thread.
    const int r0 = tid >> 2, q0 = (tid & 3) << 3;
    const int r1 = r0 + 64;

    auto issue_stage = [&](int stage, int k0) {
        uint32_t st = sbase + stage * STAGE_ELEMS * 2;
        uint32_t dAhi = st;
        uint32_t dAlo = st + SPLIT_TILE * 2;
        uint32_t dBhi = st + 2 * SPLIT_TILE * 2;
        uint32_t dBlo = st + 3 * SPLIT_TILE * 2;
        CP16(dAhi + (r0 * LDSP + q0) * 2, &Ahi[(size_t)(bm + r0) * K + k0 + q0]);
        CP16(dAhi + (r1 * LDSP + q0) * 2, &Ahi[(size_t)(bm + r1) * K + k0 + q0]);
        CP16(dAlo + (r0 * LDSP + q0) * 2, &Alo[(size_t)(bm + r0) * K + k0 + q0]);
        CP16(dAlo + (r1 * LDSP + q0) * 2, &Alo[(size_t)(bm + r1) * K + k0 + q0]);
        CP16(dBhi + (r0 * LDSP + q0) * 2, &Bhi[(size_t)(bn + r0) * K + k0 + q0]);
        CP16(dBhi + (r1 * LDSP + q0) * 2, &Bhi[(size_t)(bn + r1) * K + k0 + q0]);
        CP16(dBlo + (r0 * LDSP + q0) * 2, &Blo[(size_t)(bn + r0) * K + k0 + q0]);
        CP16(dBlo + (r1 * LDSP + q0) * 2, &Blo[(size_t)(bn + r1) * K + k0 + q0]);
    };

    // ldmatrix lane addressing
    const int rowA = (lane & 7) + ((lane >> 3) & 1) * 8;
    const int colA = ((lane >> 4) & 1) * 8;
    const int rowB = ((lane >> 4) & 1) * 8 + (lane & 7);
    const int colB = ((lane >> 3) & 1) * 8;

    constexpr int NCHUNK = K / 32;
    issue_stage(0, 0); CP_COMMIT();
    issue_stage(1, 32); CP_COMMIT();

    for (int ci = 0; ci < NCHUNK; ci++) {
        CP_WAIT(1);
        __syncthreads();
        if (ci + 2 < NCHUNK) issue_stage((ci + 2) % NSTAGE, (ci + 2) * 32);
        CP_COMMIT();   // constant group count (empty groups at tail)

        uint32_t st = sbase + (ci % NSTAGE) * STAGE_ELEMS * 2;
        uint32_t uAhi = st, uAlo = st + SPLIT_TILE * 2;
        uint32_t uBhi = st + 2 * SPLIT_TILE * 2, uBlo = st + 3 * SPLIT_TILE * 2;

        #pragma unroll
        for (int ks = 0; ks < 32; ks += 16) {
            uint32_t ahi[4][4], alo[4][4], bhi[4][2], blo[4][2];
            #pragma unroll
            for (int mt = 0; mt < 4; mt++) {
                uint32_t off = ((warpM * 64 + mt * 16 + rowA) * LDSP + colA + ks) * 2;
                LDSM4(ahi[mt][0], ahi[mt][1], ahi[mt][2], ahi[mt][3], uAhi + off);
                LDSM4(alo[mt][0], alo[mt][1], alo[mt][2], alo[mt][3], uAlo + off);
            }
            #pragma unroll
            for (int p = 0; p < 2; p++) {
                uint32_t off = ((warpN * 32 + p * 16 + rowB) * LDSP + colB + ks) * 2;
                LDSM4(bhi[2 * p][0], bhi[2 * p][1], bhi[2 * p + 1][0], bhi[2 * p + 1][1], uBhi + off);
                LDSM4(blo[2 * p][0], blo[2 * p][1], blo[2 * p + 1][0], blo[2 * p + 1][1], uBlo + off);
            }
            #pragma unroll
            for (int mt = 0; mt < 4; mt++)
                #pragma unroll
                for (int nt = 0; nt < 4; nt++) {
                    MMA16816(acc[mt][nt], ahi[mt], bhi[nt]);
                    MMA16816(acc[mt][nt], alo[mt], bhi[nt]);
                    MMA16816(acc[mt][nt], ahi[mt], blo[nt]);
                }
        }
    }

    // writeout
    #pragma unroll
    for (int mt = 0; mt < 4; mt++) {
        int rr = bm + warpM * 64 + mt * 16 + (lane >> 2);
        #pragma unroll
        for (int nt = 0; nt < 4; nt++) {
            int c = bn + warpN * 32 + nt * 8 + (lane & 3) * 2;
            float2 v0 = make_float2(acc[mt][nt][0], acc[mt][nt][1]);
            float2 v1 = make_float2(acc[mt][nt][2], acc[mt][nt][3]);
            *reinterpret_cast<float2*>(&C[(size_t)rr * N + c]) = v0;
            *reinterpret_cast<float2*>(&C[(size_t)(rr + 8) * N + c]) = v1;
        }
    }
}

// ---------------- layer-1 elementwise: warp per row, b1 in registers ----------------
__global__ void __launch_bounds__(256) ew1_warp(const float* __restrict__ b1) {
    const int wid = threadIdx.x >> 5, lane = threadIdx.x & 31;
    const int row = blockIdx.x * 8 + wid;
    const float maxn = 1.0f - 4e-3f;
    const float* mx = g_c + (size_t)row * DH;

    float mv[16], bv[16];
    const float4* m4 = reinterpret_cast<const float4*>(mx);
    const float4* b4 = reinterpret_cast<const float4*>(b1);
    #pragma unroll
    for (int i = 0; i < 4; i++) {
        float4 a = m4[lane * 4 + i];
        mv[4 * i] = a.x; mv[4 * i + 1] = a.y; mv[4 * i + 2] = a.z; mv[4 * i + 3] = a.w;
        float4 b = b4[lane * 4 + i];
        bv[4 * i] = b.x; bv[4 * i + 1] = b.y; bv[4 * i + 2] = b.z; bv[4 * i + 3] = b.w;
    }
    float pm = 0.f, pvb = 0.f, py = 0.f;
    #pragma unroll
    for (int i = 0; i < 16; i++) {
        pm  = fmaf(mv[i], mv[i], pm);
        pvb = fmaf(mv[i], bv[i], pvb);
        py  = fmaf(bv[i], bv[i], py);
    }
    float mxn2 = wred(pm), vb = wred(pvb), y2 = wred(py);

    float xn  = fmaxf(sqrtf(g_xn2[row]), 1e-15f);
    float mxn = fmaxf(sqrtf(mxn2), 1e-15f);
    float ns  = tanh_fast(mxn / xn * artanh_fast(xn));
    float s   = ns / mxn;
    float f1  = ns > maxn ? maxn / ns : 1.f;
    float sc1 = s * f1;
    float ncl = fminf(ns, maxn);
    float x2  = ncl * ncl;
    float xy  = sc1 * vb;
    float den = fmaxf(1.f + 2.f * xy + x2 * y2, 1e-15f);
    float chv = (1.f + 2.f * xy + y2) / den;
    float cb  = (1.f - x2) / den;
    float al  = chv * sc1, be = cb;
    float np2 = al * al * mxn2 + 2.f * al * be * vb + be * be * y2;
    float np  = fmaxf(sqrtf(np2), 1e-15f);
    float f2  = np > maxn ? maxn / np : 1.f;
    float nn  = fminf(np, maxn);
    float gg  = artanh_fast(nn) / nn * f2;

    float w[16], pw = 0.f;
    #pragma unroll
    for (int i = 0; i < 16; i++) {
        w[i] = tanh_fast(gg * fmaf(al, mv[i], be * bv[i]));
        pw = fmaf(w[i], w[i], pw);
    }
    float wn2 = wred(pw);
    float wn = fmaxf(sqrtf(wn2), 1e-15f);
    float tn = tanh_fast(wn);
    float hc = fminf(tn, maxn);
    float e3 = hc / wn;
    if (lane == 0) g_hn2[row] = hc * hc;

    uint32_t ph[8], pl[8];
    #pragma unroll
    for (int i = 0; i < 8; i++) {
        float v0 = e3 * w[2 * i], v1 = e3 * w[2 * i + 1];
        __nv_bfloat16 h0 = __float2bfloat16(v0), h1 = __float2bfloat16(v1);
        __nv_bfloat16 l0 = __float2bfloat16(v0 - __bfloat162float(h0));
        __nv_bfloat16 l1 = __float2bfloat16(v1 - __bfloat162float(h1));
        ph[i] = (uint32_t)__bfloat16_as_ushort(h0) | ((uint32_t)__bfloat16_as_ushort(h1) << 16);
        pl[i] = (uint32_t)__bfloat16_as_ushort(l0) | ((uint32_t)__bfloat16_as_ushort(l1) << 16);
    }
    uint4* dh = reinterpret_cast<uint4*>(g_hhi + (size_t)row * DH + lane * 16);
    uint4* dl = reinterpret_cast<uint4*>(g_hlo + (size_t)row * DH + lane * 16);
    dh[0] = make_uint4(ph[0], ph[1], ph[2], ph[3]);
    dh[1] = make_uint4(ph[4], ph[5], ph[6], ph[7]);
    dl[0] = make_uint4(pl[0], pl[1], pl[2], pl[3]);
    dl[1] = make_uint4(pl[4], pl[5], pl[6], pl[7]);
}

// ---------------- layer-2 elementwise: warp per row ----------------
__global__ void __launch_bounds__(256) ew2_warp(const float* __restrict__ b2,
                                                float* __restrict__ out) {
    const int wid = threadIdx.x >> 5, lane = threadIdx.x & 31;
    const int row = blockIdx.x * 8 + wid;
    const float maxn = 1.0f - 4e-3f;
    const float* mx = g_c + (size_t)row * DOUT;

    float4 a = reinterpret_cast<const float4*>(mx)[lane];
    float4 b = reinterpret_cast<const float4*>(b2)[lane];
    float mv[4] = {a.x, a.y, a.z, a.w};
    float bv[4] = {b.x, b.y, b.z, b.w};
    float pm = 0.f, pvb = 0.f, py = 0.f;
    #pragma unroll
    for (int i = 0; i < 4; i++) {
        pm  = fmaf(mv[i], mv[i], pm);
        pvb = fmaf(mv[i], bv[i], pvb);
        py  = fmaf(bv[i], bv[i], py);
    }
    float mxn2 = wred(pm), vb = wred(pvb), y2 = wred(py);

    float xn  = fmaxf(sqrtf(g_hn2[row]), 1e-15f);
    float mxn = fmaxf(sqrtf(mxn2), 1e-15f);
    float ns  = tanh_fast(mxn / xn * artanh_fast(xn));
    float s   = ns / mxn;
    float f1  = ns > maxn ? maxn / ns : 1.f;
    float sc1 = s * f1;
    float ncl = fminf(ns, maxn);
    float x2  = ncl * ncl;
    float xy  = sc1 * vb;
    float den = fmaxf(1.f + 2.f * xy + x2 * y2, 1e-15f);
    float chv = (1.f + 2.f * xy + y2) / den;
    float cb  = (1.f - x2) / den;
    float al  = chv * sc1, be = cb;
    float np2 = al * al * mxn2 + 2.f * al * be * vb + be * be * y2;
    float np  = fmaxf(sqrtf(np2), 1e-15f);
    float f2  = np > maxn ? maxn / np : 1.f;

    float4 o;
    o.x = f2 * fmaf(al, mv[0], be * bv[0]);
    o.y = f2 * fmaf(al, mv[1], be * bv[1]);
    o.z = f2 * fmaf(al, mv[2], be * bv[2]);
    o.w = f2 * fmaf(al, mv[3], be * bv[3]);
    reinterpret_cast<float4*>(out + (size_t)row * DOUT)[lane] = o;
}

// ---------------- launch ----------------
extern "C" void kernel_launch(void* const* d_in, const int* in_sizes, int n_in,
                              void* d_out, int out_size) {
    const float* x  = (const float*)d_in[0];
    const float* W1 = (const float*)d_in[1];
    const float* b1 = (const float*)d_in[2];
    const float* W2 = (const float*)d_in[3];
    const float* b2 = (const float*)d_in[4];
    float* out = (float*)d_out;

    __nv_bfloat16 *xhi, *xlo, *w1hi, *w1lo, *w2hi, *w2lo, *hhi, *hlo;
    float* c;
    cudaGetSymbolAddress((void**)&xhi, g_xhi);
    cudaGetSymbolAddress((void**)&xlo, g_xlo);
    cudaGetSymbolAddress((void**)&w1hi, g_w1hi);
    cudaGetSymbolAddress((void**)&w1lo, g_w1lo);
    cudaGetSymbolAddress((void**)&w2hi, g_w2hi);
    cudaGetSymbolAddress((void**)&w2lo, g_w2lo);
    cudaGetSymbolAddress((void**)&hhi, g_hhi);
    cudaGetSymbolAddress((void**)&hlo, g_hlo);
    cudaGetSymbolAddress((void**)&c, g_c);

    cudaFuncSetAttribute(mma_gemm<DIN, DH>, cudaFuncAttributeMaxDynamicSharedMemorySize, GEMM_SMEM);
    cudaFuncSetAttribute(mma_gemm<DH, DOUT>, cudaFuncAttributeMaxDynamicSharedMemorySize, GEMM_SMEM);

    convert_x_kernel<<<BATCH / 8, 256>>>(x);
    convert_w_kernel<<<(DH * DIN + 255) / 256, 256>>>(W1, W2);

    // layer 1: mx1 = x @ W1^T  [B, 512]
    mma_gemm<DIN, DH><<<dim3(DH / 128, BATCH / 128), 256, GEMM_SMEM>>>(xhi, xlo, w1hi, w1lo, c);
    ew1_warp<<<BATCH / 8, 256>>>(b1);

    // layer 2: mx2 = h @ W2^T  [B, 128]
    mma_gemm<DH, DOUT><<<dim3(DOUT / 128, BATCH / 128), 256, GEMM_SMEM>>>(hhi, hlo, w2hi, w2lo, c);
    ew2_warp<<<BATCH / 8, 256>>>(b2, out);
}

// round 15
// speedup vs baseline: 1.0486x; 1.0486x over previous
#include <cuda_runtime.h>
#include <cuda_bf16.h>
#include <stdint.h>
#include <math.h>

#define BATCH 65536
#define DIN 256
#define DH 512
#define DOUT 128

// ---------------- scratch (__device__ globals; no cudaMalloc allowed) ----------------
__device__ __nv_bfloat16 g_xhi[(size_t)BATCH * DIN];
__device__ __nv_bfloat16 g_xlo[(size_t)BATCH * DIN];
__device__ __nv_bfloat16 g_w1hi[DH * DIN], g_w1lo[DH * DIN];
__device__ __nv_bfloat16 g_w2hi[DOUT * DH], g_w2lo[DOUT * DH];
__device__ __nv_bfloat16 g_hhi[(size_t)BATCH * DH];
__device__ __nv_bfloat16 g_hlo[(size_t)BATCH * DH];
__device__ float g_c[(size_t)BATCH * DH];          // fp32 GEMM output (reused by both layers)
__device__ float g_xn2[BATCH], g_hn2[BATCH];

__device__ __forceinline__ float artanh_fast(float z) {
    z = fminf(fmaxf(z, -1.0f + 1e-7f), 1.0f - 1e-7f);
    return 0.5f * __logf((1.0f + z) / (1.0f - z));
}
__device__ __forceinline__ float tanh_fast(float x) {
    float ax = fabsf(x);
    float t = __expf(-2.0f * ax);
    float r = (1.0f - t) / (1.0f + t);
    return copysignf(r, x);
}
__device__ __forceinline__ float wred(float v) {
    #pragma unroll
    for (int o = 16; o > 0; o >>= 1) v += __shfl_xor_sync(0xffffffffu, v, o);
    return v;
}
__device__ __forceinline__ uint32_t smem_u32(const void* p) {
    uint32_t a;
    asm("{ .reg .u64 t; cvta.to.shared.u64 t, %1; cvt.u32.u64 %0, t; }" : "=r"(a) : "l"(p));
    return a;
}

#define LDSM4(r0, r1, r2, r3, addr)                                               \
    asm volatile("ldmatrix.sync.aligned.m8n8.x4.shared.b16 {%0,%1,%2,%3}, [%4];"  \
                 : "=r"(r0), "=r"(r1), "=r"(r2), "=r"(r3) : "r"(addr))

#define MMA16816(c, a, b)                                                          \
    asm volatile("mma.sync.aligned.m16n8k16.row.col.f32.bf16.bf16.f32 "            \
                 "{%0,%1,%2,%3}, {%4,%5,%6,%7}, {%8,%9}, {%0,%1,%2,%3};"           \
                 : "+f"((c)[0]), "+f"((c)[1]), "+f"((c)[2]), "+f"((c)[3])          \
                 : "r"((a)[0]), "r"((a)[1]), "r"((a)[2]), "r"((a)[3]),             \
                   "r"((b)[0]), "r"((b)[1]))

#define CP16(dst, src)                                                             \
    asm volatile("cp.async.cg.shared.global [%0], [%1], 16;" :: "r"(dst), "l"(src))
#define CP_COMMIT() asm volatile("cp.async.commit_group;" ::: "memory")
#define CP_WAIT(n)  asm volatile("cp.async.wait_group %0;" :: "n"(n) : "memory")

// ---------------- conversion kernels ----------------
__global__ void __launch_bounds__(256) convert_x_kernel(const float* __restrict__ x) {
    int gw = (blockIdx.x * 256 + threadIdx.x) >> 5;   // row
    int lane = threadIdx.x & 31;
    const float4* xr = reinterpret_cast<const float4*>(x + (size_t)gw * DIN);
    float s2 = 0.f;
    #pragma unroll
    for (int i = 0; i < 2; i++) {
        int q = lane + 32 * i;
        float4 v = xr[q];
        s2 += v.x * v.x + v.y * v.y + v.z * v.z + v.w * v.w;
        __nv_bfloat16 h0 = __float2bfloat16(v.x), h1 = __float2bfloat16(v.y);
        __nv_bfloat16 h2 = __float2bfloat16(v.z), h3 = __float2bfloat16(v.w);
        __nv_bfloat16 l0 = __float2bfloat16(v.x - __bfloat162float(h0));
        __nv_bfloat16 l1 = __float2bfloat16(v.y - __bfloat162float(h1));
        __nv_bfloat16 l2 = __float2bfloat16(v.z - __bfloat162float(h2));
        __nv_bfloat16 l3 = __float2bfloat16(v.w - __bfloat162float(h3));
        __nv_bfloat162* dh = reinterpret_cast<__nv_bfloat162*>(g_xhi) + ((size_t)gw * DIN >> 1) + q * 2;
        __nv_bfloat162* dl = reinterpret_cast<__nv_bfloat162*>(g_xlo) + ((size_t)gw * DIN >> 1) + q * 2;
        __nv_bfloat162 th; th.x = h0; th.y = h1; dh[0] = th;
        th.x = h2; th.y = h3; dh[1] = th;
        __nv_bfloat162 tl; tl.x = l0; tl.y = l1; dl[0] = tl;
        tl.x = l2; tl.y = l3; dl[1] = tl;
    }
    s2 = wred(s2);
    if (lane == 0) g_xn2[gw] = s2;
}

__global__ void __launch_bounds__(256) convert_w_kernel(const float* __restrict__ W1,
                                                        const float* __restrict__ W2) {
    int i = blockIdx.x * 256 + threadIdx.x;
    if (i < DH * DIN) {
        float v = W1[i];
        __nv_bfloat16 h = __float2bfloat16(v);
        g_w1hi[i] = h;
        g_w1lo[i] = __float2bfloat16(v - __bfloat162float(h));
    }
    if (i < DOUT * DH) {
        float v = W2[i];
        __nv_bfloat16 h = __float2bfloat16(v);
        g_w2hi[i] = h;
        g_w2lo[i] = __float2bfloat16(v - __bfloat162float(h));
    }
}

// ---------------- mma.sync split-bf16 GEMM, cp.async 2-stage, 2 CTAs/SM ----------------
// BM=128, BN=64, BK=32. 256 threads = 8 warps (4 in M x 2 in N), warp tile 32x32.
#define LDSP 40
#define A_TILE (128 * LDSP)     // elements
#define B_TILE (64 * LDSP)
#define STAGE_ELEMS (2 * A_TILE + 2 * B_TILE)   // Ahi, Alo, Bhi, Blo
#define GEMM_SMEM (2 * STAGE_ELEMS * 2)         // bytes (2 stages, bf16) = 61440

template<int K, int N>
__global__ void __launch_bounds__(256, 2) mma_gemm(const __nv_bfloat16* __restrict__ Ahi,
                                                   const __nv_bfloat16* __restrict__ Alo,
                                                   const __nv_bfloat16* __restrict__ Bhi,
                                                   const __nv_bfloat16* __restrict__ Blo,
                                                   float* __restrict__ C)
{
    extern __shared__ __nv_bfloat16 smem[];
    const int tid = threadIdx.x, lane = tid & 31, wid = tid >> 5;
    const int warpM = wid & 3, warpN = wid >> 2;
    const int bm = blockIdx.y * 128, bn = blockIdx.x * 64;
    const uint32_t sbase = smem_u32(smem);

    float acc[2][4][4];
    #pragma unroll
    for (int i = 0; i < 2; i++)
        #pragma unroll
        for (int j = 0; j < 4; j++)
            #pragma unroll
            for (int l = 0; l < 4; l++) acc[i][j][l] = 0.f;

    // cp.async addressing: A tiles 128x32 = 512 uint4 (2/thread), B 64x32 = 256 uint4 (1/thread)
    const int rA0 = tid >> 2, qA0 = (tid & 3) << 3;
    const int rA1 = (tid + 256) >> 2, qA1 = qA0;
    const int rB = tid >> 2, qB = (tid & 3) << 3;

    auto issue_stage = [&](int stage, int k0) {
        uint32_t st = sbase + stage * STAGE_ELEMS * 2;
        uint32_t dAhi = st, dAlo = st + A_TILE * 2;
        uint32_t dBhi = st + 2 * A_TILE * 2, dBlo = dBhi + B_TILE * 2;
        CP16(dAhi + (rA0 * LDSP + qA0) * 2, &Ahi[(size_t)(bm + rA0) * K + k0 + qA0]);
        CP16(dAhi + (rA1 * LDSP + qA1) * 2, &Ahi[(size_t)(bm + rA1) * K + k0 + qA1]);
        CP16(dAlo + (rA0 * LDSP + qA0) * 2, &Alo[(size_t)(bm + rA0) * K + k0 + qA0]);
        CP16(dAlo + (rA1 * LDSP + qA1) * 2, &Alo[(size_t)(bm + rA1) * K + k0 + qA1]);
        CP16(dBhi + (rB * LDSP + qB) * 2, &Bhi[(size_t)(bn + rB) * K + k0 + qB]);
        CP16(dBlo + (rB * LDSP + qB) * 2, &Blo[(size_t)(bn + rB) * K + k0 + qB]);
        CP_COMMIT();
    };

    // ldmatrix lane addressing
    const int rowA = (lane & 7) + ((lane >> 3) & 1) * 8;    // 0..15
    const int colA = ((lane >> 4) & 1) * 8;                 // 0 or 8
    const int rowB = warpN * 32 + ((lane >> 4) & 1) * 8 + (lane & 7);
    const int colB = ((lane >> 3) & 1) * 8;

    constexpr int NCHUNK = K / 32;
    issue_stage(0, 0);

    for (int ci = 0; ci < NCHUNK; ci++) {
        if (ci + 1 < NCHUNK) {
            issue_stage((ci + 1) & 1, (ci + 1) * 32);
            CP_WAIT(1);
        } else {
            CP_WAIT(0);
        }
        __syncthreads();

        uint32_t st = sbase + (ci & 1) * STAGE_ELEMS * 2;
        uint32_t uAhi = st, uAlo = st + A_TILE * 2;
        uint32_t uBhi = st + 2 * A_TILE * 2, uBlo = uBhi + B_TILE * 2;

        #pragma unroll
        for (int ks = 0; ks < 32; ks += 16) {
            uint32_t ahi[2][4], alo[2][4], bhi[4][2], blo[4][2];
            #pragma unroll
            for (int mt = 0; mt < 2; mt++) {
                uint32_t off = ((warpM * 32 + mt * 16 + rowA) * LDSP + colA + ks) * 2;
                LDSM4(ahi[mt][0], ahi[mt][1], ahi[mt][2], ahi[mt][3], uAhi + off);
                LDSM4(alo[mt][0], alo[mt][1], alo[mt][2], alo[mt][3], uAlo + off);
            }
            #pragma unroll
            for (int p = 0; p < 2; p++) {
                uint32_t off = ((rowB + p * 16) * LDSP + colB + ks) * 2;
                LDSM4(bhi[2 * p][0], bhi[2 * p][1], bhi[2 * p + 1][0], bhi[2 * p + 1][1], uBhi + off);
                LDSM4(blo[2 * p][0], blo[2 * p][1], blo[2 * p + 1][0], blo[2 * p + 1][1], uBlo + off);
            }
            #pragma unroll
            for (int mt = 0; mt < 2; mt++)
                #pragma unroll
                for (int nt = 0; nt < 4; nt++) {
                    MMA16816(acc[mt][nt], ahi[mt], bhi[nt]);
                    MMA16816(acc[mt][nt], alo[mt], bhi[nt]);
                    MMA16816(acc[mt][nt], ahi[mt], blo[nt]);
                }
        }
        __syncthreads();   // all warps done reading stage (ci&1) before it is rewritten
    }

    // writeout
    #pragma unroll
    for (int mt = 0; mt < 2; mt++) {
        int r0 = bm + warpM * 32 + mt * 16 + (lane >> 2);
        #pragma unroll
        for (int nt = 0; nt < 4; nt++) {
            int c = bn + warpN * 32 + nt * 8 + (lane & 3) * 2;
            float2 v0 = make_float2(acc[mt][nt][0], acc[mt][nt][1]);
            float2 v1 = make_float2(acc[mt][nt][2], acc[mt][nt][3]);
            *reinterpret_cast<float2*>(&C[(size_t)r0 * N + c]) = v0;
            *reinterpret_cast<float2*>(&C[(size_t)(r0 + 8) * N + c]) = v1;
        }
    }
}

// ---------------- layer-1 elementwise: warp per row, b1 in registers ----------------
__global__ void __launch_bounds__(256) ew1_warp(const float* __restrict__ b1) {
    const int wid = threadIdx.x >> 5, lane = threadIdx.x & 31;
    const int row = blockIdx.x * 8 + wid;
    const float maxn = 1.0f - 4e-3f;
    const float* mx = g_c + (size_t)row * DH;

    float mv[16], bv[16];
    const float4* m4 = reinterpret_cast<const float4*>(mx);
    const float4* b4 = reinterpret_cast<const float4*>(b1);
    #pragma unroll
    for (int i = 0; i < 4; i++) {
        float4 a = m4[lane * 4 + i];
        mv[4 * i] = a.x; mv[4 * i + 1] = a.y; mv[4 * i + 2] = a.z; mv[4 * i + 3] = a.w;
        float4 b = b4[lane * 4 + i];
        bv[4 * i] = b.x; bv[4 * i + 1] = b.y; bv[4 * i + 2] = b.z; bv[4 * i + 3] = b.w;
    }
    float pm = 0.f, pvb = 0.f, py = 0.f;
    #pragma unroll
    for (int i = 0; i < 16; i++) {
        pm  = fmaf(mv[i], mv[i], pm);
        pvb = fmaf(mv[i], bv[i], pvb);
        py  = fmaf(bv[i], bv[i], py);
    }
    float mxn2 = wred(pm), vb = wred(pvb), y2 = wred(py);

    float xn  = fmaxf(sqrtf(g_xn2[row]), 1e-15f);
    float mxn = fmaxf(sqrtf(mxn2), 1e-15f);
    float ns  = tanh_fast(mxn / xn * artanh_fast(xn));
    float s   = ns / mxn;
    float f1  = ns > maxn ? maxn / ns : 1.f;
    float sc1 = s * f1;
    float ncl = fminf(ns, maxn);
    float x2  = ncl * ncl;
    float xy  = sc1 * vb;
    float den = fmaxf(1.f + 2.f * xy + x2 * y2, 1e-15f);
    float chv = (1.f + 2.f * xy + y2) / den;
    float cb  = (1.f - x2) / den;
    float al  = chv * sc1, be = cb;
    float np2 = al * al * mxn2 + 2.f * al * be * vb + be * be * y2;
    float np  = fmaxf(sqrtf(np2), 1e-15f);
    float f2  = np > maxn ? maxn / np : 1.f;
    float nn  = fminf(np, maxn);
    float gg  = artanh_fast(nn) / nn * f2;

    float w[16], pw = 0.f;
    #pragma unroll
    for (int i = 0; i < 16; i++) {
        w[i] = tanh_fast(gg * fmaf(al, mv[i], be * bv[i]));
        pw = fmaf(w[i], w[i], pw);
    }
    float wn2 = wred(pw);
    float wn = fmaxf(sqrtf(wn2), 1e-15f);
    float tn = tanh_fast(wn);
    float hc = fminf(tn, maxn);
    float e3 = hc / wn;
    if (lane == 0) g_hn2[row] = hc * hc;

    uint32_t ph[8], pl[8];
    #pragma unroll
    for (int i = 0; i < 8; i++) {
        float v0 = e3 * w[2 * i], v1 = e3 * w[2 * i + 1];
        __nv_bfloat16 h0 = __float2bfloat16(v0), h1 = __float2bfloat16(v1);
        __nv_bfloat16 l0 = __float2bfloat16(v0 - __bfloat162float(h0));
        __nv_bfloat16 l1 = __float2bfloat16(v1 - __bfloat162float(h1));
        ph[i] = (uint32_t)__bfloat16_as_ushort(h0) | ((uint32_t)__bfloat16_as_ushort(h1) << 16);
        pl[i] = (uint32_t)__bfloat16_as_ushort(l0) | ((uint32_t)__bfloat16_as_ushort(l1) << 16);
    }
    uint4* dh = reinterpret_cast<uint4*>(g_hhi + (size_t)row * DH + lane * 16);
    uint4* dl = reinterpret_cast<uint4*>(g_hlo + (size_t)row * DH + lane * 16);
    dh[0] = make_uint4(ph[0], ph[1], ph[2], ph[3]);
    dh[1] = make_uint4(ph[4], ph[5], ph[6], ph[7]);
    dl[0] = make_uint4(pl[0], pl[1], pl[2], pl[3]);
    dl[1] = make_uint4(pl[4], pl[5], pl[6], pl[7]);
}

// ---------------- layer-2 elementwise: warp per row ----------------
__global__ void __launch_bounds__(256) ew2_warp(const float* __restrict__ b2,
                                                float* __restrict__ out) {
    const int wid = threadIdx.x >> 5, lane = threadIdx.x & 31;
    const int row = blockIdx.x * 8 + wid;
    const float maxn = 1.0f - 4e-3f;
    const float* mx = g_c + (size_t)row * DOUT;

    float4 a = reinterpret_cast<const float4*>(mx)[lane];
    float4 b = reinterpret_cast<const float4*>(b2)[lane];
    float mv[4] = {a.x, a.y, a.z, a.w};
    float bv[4] = {b.x, b.y, b.z, b.w};
    float pm = 0.f, pvb = 0.f, py = 0.f;
    #pragma unroll
    for (int i = 0; i < 4; i++) {
        pm  = fmaf(mv[i], mv[i], pm);
        pvb = fmaf(mv[i], bv[i], pvb);
        py  = fmaf(bv[i], bv[i], py);
    }
    float mxn2 = wred(pm), vb = wred(pvb), y2 = wred(py);

    float xn  = fmaxf(sqrtf(g_hn2[row]), 1e-15f);
    float mxn = fmaxf(sqrtf(mxn2), 1e-15f);
    float ns  = tanh_fast(mxn / xn * artanh_fast(xn));
    float s   = ns / mxn;
    float f1  = ns > maxn ? maxn / ns : 1.f;
    float sc1 = s * f1;
    float ncl = fminf(ns, maxn);
    float x2  = ncl * ncl;
    float xy  = sc1 * vb;
    float den = fmaxf(1.f + 2.f * xy + x2 * y2, 1e-15f);
    float chv = (1.f + 2.f * xy + y2) / den;
    float cb  = (1.f - x2) / den;
    float al  = chv * sc1, be = cb;
    float np2 = al * al * mxn2 + 2.f * al * be * vb + be * be * y2;
    float np  = fmaxf(sqrtf(np2), 1e-15f);
    float f2  = np > maxn ? maxn / np : 1.f;

    float4 o;
    o.x = f2 * fmaf(al, mv[0], be * bv[0]);
    o.y = f2 * fmaf(al, mv[1], be * bv[1]);
    o.z = f2 * fmaf(al, mv[2], be * bv[2]);
    o.w = f2 * fmaf(al, mv[3], be * bv[3]);
    reinterpret_cast<float4*>(out + (size_t)row * DOUT)[lane] = o;
}

// ---------------- launch ----------------
extern "C" void kernel_launch(void* const* d_in, const int* in_sizes, int n_in,
                              void* d_out, int out_size) {
    const float* x  = (const float*)d_in[0];
    const float* W1 = (const float*)d_in[1];
    const float* b1 = (const float*)d_in[2];
    const float* W2 = (const float*)d_in[3];
    const float* b2 = (const float*)d_in[4];
    float* out = (float*)d_out;

    __nv_bfloat16 *xhi, *xlo, *w1hi, *w1lo, *w2hi, *w2lo, *hhi, *hlo;
    float* c;
    cudaGetSymbolAddress((void**)&xhi, g_xhi);
    cudaGetSymbolAddress((void**)&xlo, g_xlo);
    cudaGetSymbolAddress((void**)&w1hi, g_w1hi);
    cudaGetSymbolAddress((void**)&w1lo, g_w1lo);
    cudaGetSymbolAddress((void**)&w2hi, g_w2hi);
    cudaGetSymbolAddress((void**)&w2lo, g_w2lo);
    cudaGetSymbolAddress((void**)&hhi, g_hhi);
    cudaGetSymbolAddress((void**)&hlo, g_hlo);
    cudaGetSymbolAddress((void**)&c, g_c);

    cudaFuncSetAttribute(mma_gemm<DIN, DH>, cudaFuncAttributeMaxDynamicSharedMemorySize, GEMM_SMEM);
    cudaFuncSetAttribute(mma_gemm<DH, DOUT>, cudaFuncAttributeMaxDynamicSharedMemorySize, GEMM_SMEM);

    convert_x_kernel<<<BATCH / 8, 256>>>(x);
    convert_w_kernel<<<(DH * DIN + 255) / 256, 256>>>(W1, W2);

    // layer 1: mx1 = x @ W1^T  [B, 512]
    mma_gemm<DIN, DH><<<dim3(DH / 64, BATCH / 128), 256, GEMM_SMEM>>>(xhi, xlo, w1hi, w1lo, c);
    ew1_warp<<<BATCH / 8, 256>>>(b1);

    // layer 2: mx2 = h @ W2^T  [B, 128]
    mma_gemm<DH, DOUT><<<dim3(DOUT / 64, BATCH / 128), 256, GEMM_SMEM>>>(hhi, hlo, w2hi, w2lo, c);
    ew2_warp<<<BATCH / 8, 256>>>(b2, out);
}

// round 16
// speedup vs baseline: 1.0555x; 1.0065x over previous
#include <cuda_runtime.h>
#include <cuda_bf16.h>
#include <stdint.h>
#include <math.h>

#define BATCH 65536
#define DIN 256
#define DH 512
#define DOUT 128

// ---------------- scratch (__device__ globals; no cudaMalloc allowed) ----------------
__device__ __nv_bfloat16 g_xhi[(size_t)BATCH * DIN];
__device__ __nv_bfloat16 g_xlo[(size_t)BATCH * DIN];
__device__ __nv_bfloat16 g_w1hi[DH * DIN], g_w1lo[DH * DIN];
__device__ __nv_bfloat16 g_w2hi[DOUT * DH], g_w2lo[DOUT * DH];
__device__ __nv_bfloat16 g_hhi[(size_t)BATCH * DH];
__device__ __nv_bfloat16 g_hlo[(size_t)BATCH * DH];
__device__ float g_c[(size_t)BATCH * DH];          // fp32 GEMM1 output
__device__ float g_xn2[BATCH], g_hn2[BATCH];

__device__ __forceinline__ float artanh_fast(float z) {
    z = fminf(fmaxf(z, -1.0f + 1e-7f), 1.0f - 1e-7f);
    return 0.5f * __logf((1.0f + z) / (1.0f - z));
}
__device__ __forceinline__ float tanh_fast(float x) {
    float ax = fabsf(x);
    float t = __expf(-2.0f * ax);
    float r = (1.0f - t) / (1.0f + t);
    return copysignf(r, x);
}
__device__ __forceinline__ float wred(float v) {
    #pragma unroll
    for (int o = 16; o > 0; o >>= 1) v += __shfl_xor_sync(0xffffffffu, v, o);
    return v;
}
__device__ __forceinline__ uint32_t smem_u32(const void* p) {
    uint32_t a;
    asm("{ .reg .u64 t; cvta.to.shared.u64 t, %1; cvt.u32.u64 %0, t; }" : "=r"(a) : "l"(p));
    return a;
}

#define LDSM4(r0, r1, r2, r3, addr)                                               \
    asm volatile("ldmatrix.sync.aligned.m8n8.x4.shared.b16 {%0,%1,%2,%3}, [%4];"  \
                 : "=r"(r0), "=r"(r1), "=r"(r2), "=r"(r3) : "r"(addr))

#define MMA16816(c, a, b)                                                          \
    asm volatile("mma.sync.aligned.m16n8k16.row.col.f32.bf16.bf16.f32 "            \
                 "{%0,%1,%2,%3}, {%4,%5,%6,%7}, {%8,%9}, {%0,%1,%2,%3};"           \
                 : "+f"((c)[0]), "+f"((c)[1]), "+f"((c)[2]), "+f"((c)[3])          \
                 : "r"((a)[0]), "r"((a)[1]), "r"((a)[2]), "r"((a)[3]),             \
                   "r"((b)[0]), "r"((b)[1]))

#define CP16(dst, src)                                                             \
    asm volatile("cp.async.cg.shared.global [%0], [%1], 16;" :: "r"(dst), "l"(src))
#define CP_COMMIT() asm volatile("cp.async.commit_group;" ::: "memory")
#define CP_WAIT(n)  asm volatile("cp.async.wait_group %0;" :: "n"(n) : "memory")

// ---------------- conversion kernels ----------------
__global__ void __launch_bounds__(256) convert_x_kernel(const float* __restrict__ x) {
    int gw = (blockIdx.x * 256 + threadIdx.x) >> 5;   // row
    int lane = threadIdx.x & 31;
    const float4* xr = reinterpret_cast<const float4*>(x + (size_t)gw * DIN);
    float s2 = 0.f;
    #pragma unroll
    for (int i = 0; i < 2; i++) {
        int q = lane + 32 * i;
        float4 v = xr[q];
        s2 += v.x * v.x + v.y * v.y + v.z * v.z + v.w * v.w;
        __nv_bfloat16 h0 = __float2bfloat16(v.x), h1 = __float2bfloat16(v.y);
        __nv_bfloat16 h2 = __float2bfloat16(v.z), h3 = __float2bfloat16(v.w);
        __nv_bfloat16 l0 = __float2bfloat16(v.x - __bfloat162float(h0));
        __nv_bfloat16 l1 = __float2bfloat16(v.y - __bfloat162float(h1));
        __nv_bfloat16 l2 = __float2bfloat16(v.z - __bfloat162float(h2));
        __nv_bfloat16 l3 = __float2bfloat16(v.w - __bfloat162float(h3));
        __nv_bfloat162* dh = reinterpret_cast<__nv_bfloat162*>(g_xhi) + ((size_t)gw * DIN >> 1) + q * 2;
        __nv_bfloat162* dl = reinterpret_cast<__nv_bfloat162*>(g_xlo) + ((size_t)gw * DIN >> 1) + q * 2;
        __nv_bfloat162 th; th.x = h0; th.y = h1; dh[0] = th;
        th.x = h2; th.y = h3; dh[1] = th;
        __nv_bfloat162 tl; tl.x = l0; tl.y = l1; dl[0] = tl;
        tl.x = l2; tl.y = l3; dl[1] = tl;
    }
    s2 = wred(s2);
    if (lane == 0) g_xn2[gw] = s2;
}

__global__ void __launch_bounds__(256) convert_w_kernel(const float* __restrict__ W1,
                                                        const float* __restrict__ W2) {
    int i = blockIdx.x * 256 + threadIdx.x;
    if (i < DH * DIN) {
        float v = W1[i];
        __nv_bfloat16 h = __float2bfloat16(v);
        g_w1hi[i] = h;
        g_w1lo[i] = __float2bfloat16(v - __bfloat162float(h));
    }
    if (i < DOUT * DH) {
        float v = W2[i];
        __nv_bfloat16 h = __float2bfloat16(v);
        g_w2hi[i] = h;
        g_w2lo[i] = __float2bfloat16(v - __bfloat162float(h));
    }
}

// ---------------- GEMM1: mma.sync split-bf16, cp.async 2-stage (R5 config) ----------------
// BM=128, BN=64, BK=32. 256 threads = 8 warps (4 in M x 2 in N), warp tile 32x32.
#define LDSP 40
#define A_TILE (128 * LDSP)     // elements
#define B_TILE (64 * LDSP)
#define STAGE_ELEMS (2 * A_TILE + 2 * B_TILE)   // Ahi, Alo, Bhi, Blo
#define GEMM_SMEM (2 * STAGE_ELEMS * 2)         // bytes = 61440

template<int K, int N>
__global__ void __launch_bounds__(256, 2) mma_gemm(const __nv_bfloat16* __restrict__ Ahi,
                                                   const __nv_bfloat16* __restrict__ Alo,
                                                   const __nv_bfloat16* __restrict__ Bhi,
                                                   const __nv_bfloat16* __restrict__ Blo,
                                                   float* __restrict__ C)
{
    extern __shared__ __nv_bfloat16 smem[];
    const int tid = threadIdx.x, lane = tid & 31, wid = tid >> 5;
    const int warpM = wid & 3, warpN = wid >> 2;
    const int bm = blockIdx.y * 128, bn = blockIdx.x * 64;
    const uint32_t sbase = smem_u32(smem);

    float acc[2][4][4];
    #pragma unroll
    for (int i = 0; i < 2; i++)
        #pragma unroll
        for (int j = 0; j < 4; j++)
            #pragma unroll
            for (int l = 0; l < 4; l++) acc[i][j][l] = 0.f;

    const int rA0 = tid >> 2, qA0 = (tid & 3) << 3;
    const int rA1 = (tid + 256) >> 2, qA1 = qA0;
    const int rB = tid >> 2, qB = (tid & 3) << 3;

    auto issue_stage = [&](int stage, int k0) {
        uint32_t st = sbase + stage * STAGE_ELEMS * 2;
        uint32_t dAhi = st, dAlo = st + A_TILE * 2;
        uint32_t dBhi = st + 2 * A_TILE * 2, dBlo = dBhi + B_TILE * 2;
        CP16(dAhi + (rA0 * LDSP + qA0) * 2, &Ahi[(size_t)(bm + rA0) * K + k0 + qA0]);
        CP16(dAhi + (rA1 * LDSP + qA1) * 2, &Ahi[(size_t)(bm + rA1) * K + k0 + qA1]);
        CP16(dAlo + (rA0 * LDSP + qA0) * 2, &Alo[(size_t)(bm + rA0) * K + k0 + qA0]);
        CP16(dAlo + (rA1 * LDSP + qA1) * 2, &Alo[(size_t)(bm + rA1) * K + k0 + qA1]);
        CP16(dBhi + (rB * LDSP + qB) * 2, &Bhi[(size_t)(bn + rB) * K + k0 + qB]);
        CP16(dBlo + (rB * LDSP + qB) * 2, &Blo[(size_t)(bn + rB) * K + k0 + qB]);
        CP_COMMIT();
    };

    const int rowA = (lane & 7) + ((lane >> 3) & 1) * 8;
    const int colA = ((lane >> 4) & 1) * 8;
    const int rowB = warpN * 32 + ((lane >> 4) & 1) * 8 + (lane & 7);
    const int colB = ((lane >> 3) & 1) * 8;

    constexpr int NCHUNK = K / 32;
    issue_stage(0, 0);

    for (int ci = 0; ci < NCHUNK; ci++) {
        if (ci + 1 < NCHUNK) {
            issue_stage((ci + 1) & 1, (ci + 1) * 32);
            CP_WAIT(1);
        } else {
            CP_WAIT(0);
        }
        __syncthreads();

        uint32_t st = sbase + (ci & 1) * STAGE_ELEMS * 2;
        uint32_t uAhi = st, uAlo = st + A_TILE * 2;
        uint32_t uBhi = st + 2 * A_TILE * 2, uBlo = uBhi + B_TILE * 2;

        #pragma unroll
        for (int ks = 0; ks < 32; ks += 16) {
            uint32_t ahi[2][4], alo[2][4], bhi[4][2], blo[4][2];
            #pragma unroll
            for (int mt = 0; mt < 2; mt++) {
                uint32_t off = ((warpM * 32 + mt * 16 + rowA) * LDSP + colA + ks) * 2;
                LDSM4(ahi[mt][0], ahi[mt][1], ahi[mt][2], ahi[mt][3], uAhi + off);
                LDSM4(alo[mt][0], alo[mt][1], alo[mt][2], alo[mt][3], uAlo + off);
            }
            #pragma unroll
            for (int p = 0; p < 2; p++) {
                uint32_t off = ((rowB + p * 16) * LDSP + colB + ks) * 2;
                LDSM4(bhi[2 * p][0], bhi[2 * p][1], bhi[2 * p + 1][0], bhi[2 * p + 1][1], uBhi + off);
                LDSM4(blo[2 * p][0], blo[2 * p][1], blo[2 * p + 1][0], blo[2 * p + 1][1], uBlo + off);
            }
            #pragma unroll
            for (int mt = 0; mt < 2; mt++)
                #pragma unroll
                for (int nt = 0; nt < 4; nt++) {
                    MMA16816(acc[mt][nt], ahi[mt], bhi[nt]);
                    MMA16816(acc[mt][nt], alo[mt], bhi[nt]);
                    MMA16816(acc[mt][nt], ahi[mt], blo[nt]);
                }
        }
        __syncthreads();
    }

    #pragma unroll
    for (int mt = 0; mt < 2; mt++) {
        int r0 = bm + warpM * 32 + mt * 16 + (lane >> 2);
        #pragma unroll
        for (int nt = 0; nt < 4; nt++) {
            int c = bn + warpN * 32 + nt * 8 + (lane & 3) * 2;
            float2 v0 = make_float2(acc[mt][nt][0], acc[mt][nt][1]);
            float2 v1 = make_float2(acc[mt][nt][2], acc[mt][nt][3]);
            *reinterpret_cast<float2*>(&C[(size_t)r0 * N + c]) = v0;
            *reinterpret_cast<float2*>(&C[(size_t)(r0 + 8) * N + c]) = v1;
        }
    }
}

// ---------------- GEMM2 fused with layer-2 hyperbolic epilogue ----------------
// BM=128, BN=128 (= full DOUT, single N-pass), BK=32. 8 warps (2M x 4N), warp tile 64x32.
// Mainloop identical to the R12-verified BN=128 config; epilogue = ew2 math from registers.
#define G2_TILE (128 * LDSP)                   // elements per split tile (A or B)
#define G2_STAGE (4 * G2_TILE)                 // Ahi | Alo | Bhi | Blo
#define G2_SMEM (2 * G2_STAGE * 2)             // bytes = 81920

__global__ void __launch_bounds__(256, 1) gemm2_fused(const __nv_bfloat16* __restrict__ Ahi,
                                                      const __nv_bfloat16* __restrict__ Alo,
                                                      const __nv_bfloat16* __restrict__ Bhi,
                                                      const __nv_bfloat16* __restrict__ Blo,
                                                      const float* __restrict__ b2,
                                                      float* __restrict__ out)
{
    constexpr int K = DH;
    extern __shared__ __nv_bfloat16 smem[];
    const int tid = threadIdx.x, lane = tid & 31, wid = tid >> 5;
    const int warpM = wid >> 2, warpN = wid & 3;        // 2 x 4
    const int bm = blockIdx.y * 128;
    const uint32_t sbase = smem_u32(smem);
    const float maxn = 1.0f - 4e-3f;

    float acc[4][4][4];
    #pragma unroll
    for (int i = 0; i < 4; i++)
        #pragma unroll
        for (int j = 0; j < 4; j++)
            #pragma unroll
            for (int l = 0; l < 4; l++) acc[i][j][l] = 0.f;

    // cp.async: each tile 128 rows x 32 cols = 512 uint4, 2 per thread
    const int r0 = tid >> 2, q0 = (tid & 3) << 3;
    const int r1 = r0 + 64;

    auto issue_stage = [&](int stage, int k0) {
        uint32_t st = sbase + stage * G2_STAGE * 2;
        uint32_t dAhi = st;
        uint32_t dAlo = st + G2_TILE * 2;
        uint32_t dBhi = st + 2 * G2_TILE * 2;
        uint32_t dBlo = st + 3 * G2_TILE * 2;
        CP16(dAhi + (r0 * LDSP + q0) * 2, &Ahi[(size_t)(bm + r0) * K + k0 + q0]);
        CP16(dAhi + (r1 * LDSP + q0) * 2, &Ahi[(size_t)(bm + r1) * K + k0 + q0]);
        CP16(dAlo + (r0 * LDSP + q0) * 2, &Alo[(size_t)(bm + r0) * K + k0 + q0]);
        CP16(dAlo + (r1 * LDSP + q0) * 2, &Alo[(size_t)(bm + r1) * K + k0 + q0]);
        CP16(dBhi + (r0 * LDSP + q0) * 2, &Bhi[(size_t)r0 * K + k0 + q0]);
        CP16(dBhi + (r1 * LDSP + q0) * 2, &Bhi[(size_t)r1 * K + k0 + q0]);
        CP16(dBlo + (r0 * LDSP + q0) * 2, &Blo[(size_t)r0 * K + k0 + q0]);
        CP16(dBlo + (r1 * LDSP + q0) * 2, &Blo[(size_t)r1 * K + k0 + q0]);
        CP_COMMIT();
    };

    const int rowA = (lane & 7) + ((lane >> 3) & 1) * 8;
    const int colA = ((lane >> 4) & 1) * 8;
    const int rowB = ((lane >> 4) & 1) * 8 + (lane & 7);
    const int colB = ((lane >> 3) & 1) * 8;

    constexpr int NCHUNK = K / 32;   // 16
    issue_stage(0, 0);

    for (int ci = 0; ci < NCHUNK; ci++) {
        if (ci + 1 < NCHUNK) {
            issue_stage((ci + 1) & 1, (ci + 1) * 32);
            CP_WAIT(1);
        } else {
            CP_WAIT(0);
        }
        __syncthreads();

        uint32_t st = sbase + (ci & 1) * G2_STAGE * 2;
        uint32_t uAhi = st, uAlo = st + G2_TILE * 2;
        uint32_t uBhi = st + 2 * G2_TILE * 2, uBlo = st + 3 * G2_TILE * 2;

        #pragma unroll
        for (int ks = 0; ks < 32; ks += 16) {
            uint32_t ahi[4][4], alo[4][4], bhi[4][2], blo[4][2];
            #pragma unroll
            for (int mt = 0; mt < 4; mt++) {
                uint32_t off = ((warpM * 64 + mt * 16 + rowA) * LDSP + colA + ks) * 2;
                LDSM4(ahi[mt][0], ahi[mt][1], ahi[mt][2], ahi[mt][3], uAhi + off);
                LDSM4(alo[mt][0], alo[mt][1], alo[mt][2], alo[mt][3], uAlo + off);
            }
            #pragma unroll
            for (int p = 0; p < 2; p++) {
                uint32_t off = ((warpN * 32 + p * 16 + rowB) * LDSP + colB + ks) * 2;
                LDSM4(bhi[2 * p][0], bhi[2 * p][1], bhi[2 * p + 1][0], bhi[2 * p + 1][1], uBhi + off);
                LDSM4(blo[2 * p][0], blo[2 * p][1], blo[2 * p + 1][0], blo[2 * p + 1][1], uBlo + off);
            }
            #pragma unroll
            for (int mt = 0; mt < 4; mt++)
                #pragma unroll
                for (int nt = 0; nt < 4; nt++) {
                    MMA16816(acc[mt][nt], ahi[mt], bhi[nt]);
                    MMA16816(acc[mt][nt], alo[mt], bhi[nt]);
                    MMA16816(acc[mt][nt], ahi[mt], blo[nt]);
                }
        }
        __syncthreads();   // also guarantees smem free for epilogue reuse after last chunk
    }

    // ---- fused ew2 epilogue (identical math to ew2_warp, operating on register accs) ----
    float* fs  = reinterpret_cast<float*>(smem);
    float* sb2 = fs;               // [128]
    float* spm = fs + 128;         // [128][4]
    float* spv = fs + 128 + 512;   // [128][4]
    float* sal = fs + 128 + 1024;  // [128]
    float* sbe = sal + 128;        // [128]
    float* sf2 = sbe + 128;        // [128]
    float* sy2 = sf2 + 128;        // [1]

    if (tid < DOUT) sb2[tid] = b2[tid];
    __syncthreads();

    if (wid == 0) {
        float p = 0.f;
        #pragma unroll
        for (int i = 0; i < 4; i++) { float b = sb2[lane + 32 * i]; p = fmaf(b, b, p); }
        p = wred(p);
        if (lane == 0) sy2[0] = p;
    }

    #pragma unroll
    for (int mt = 0; mt < 4; mt++) {
        #pragma unroll
        for (int sub = 0; sub < 2; sub++) {
            float pm = 0.f, pv = 0.f;
            #pragma unroll
            for (int nt = 0; nt < 4; nt++) {
                float v0 = acc[mt][nt][sub * 2 + 0];
                float v1 = acc[mt][nt][sub * 2 + 1];
                int c = warpN * 32 + nt * 8 + (lane & 3) * 2;
                pm = fmaf(v0, v0, pm); pm = fmaf(v1, v1, pm);
                pv = fmaf(v0, sb2[c], pv); pv = fmaf(v1, sb2[c + 1], pv);
            }
            pm += __shfl_xor_sync(0xffffffffu, pm, 1);
            pm += __shfl_xor_sync(0xffffffffu, pm, 2);
            pv += __shfl_xor_sync(0xffffffffu, pv, 1);
            pv += __shfl_xor_sync(0xffffffffu, pv, 2);
            if ((lane & 3) == 0) {
                int row = warpM * 64 + mt * 16 + sub * 8 + (lane >> 2);
                spm[row * 4 + warpN] = pm;
                spv[row * 4 + warpN] = pv;
            }
        }
    }
    __syncthreads();

    if (tid < 128) {
        int row = tid;
        float mxn2 = spm[row * 4] + spm[row * 4 + 1] + spm[row * 4 + 2] + spm[row * 4 + 3];
        float vb   = spv[row * 4] + spv[row * 4 + 1] + spv[row * 4 + 2] + spv[row * 4 + 3];
        float y2 = sy2[0];

        float xn  = fmaxf(sqrtf(g_hn2[bm + row]), 1e-15f);
        float mxn = fmaxf(sqrtf(mxn2), 1e-15f);
        float ns  = tanh_fast(mxn / xn * artanh_fast(xn));
        float s   = ns / mxn;
        float f1  = ns > maxn ? maxn / ns : 1.f;
        float sc1 = s * f1;
        float ncl = fminf(ns, maxn);
        float x2  = ncl * ncl;
        float xy  = sc1 * vb;
        float den = fmaxf(1.f + 2.f * xy + x2 * y2, 1e-15f);
        float chv = (1.f + 2.f * xy + y2) / den;
        float cb  = (1.f - x2) / den;
        float al  = chv * sc1, be = cb;
        float np2 = al * al * mxn2 + 2.f * al * be * vb + be * be * y2;
        float np  = fmaxf(sqrtf(np2), 1e-15f);
        float f2v = np > maxn ? maxn / np : 1.f;
        sal[row] = al; sbe[row] = be; sf2[row] = f2v;
    }
    __syncthreads();

    #pragma unroll
    for (int mt = 0; mt < 4; mt++) {
        int rbase = warpM * 64 + mt * 16 + (lane >> 2);
        #pragma unroll
        for (int nt = 0; nt < 4; nt++) {
            int c = warpN * 32 + nt * 8 + (lane & 3) * 2;
            #pragma unroll
            for (int sub = 0; sub < 2; sub++) {
                int rr = rbase + sub * 8;
                float al = sal[rr], be = sbe[rr], f2v = sf2[rr];
                float o0 = f2v * fmaf(al, acc[mt][nt][sub * 2 + 0], be * sb2[c]);
                float o1 = f2v * fmaf(al, acc[mt][nt][sub * 2 + 1], be * sb2[c + 1]);
                *reinterpret_cast<float2*>(&out[(size_t)(bm + rr) * DOUT + c]) = make_float2(o0, o1);
            }
        }
    }
}

// ---------------- layer-1 elementwise: warp per row, b1 in registers ----------------
__global__ void __launch_bounds__(256) ew1_warp(const float* __restrict__ b1) {
    const int wid = threadIdx.x >> 5, lane = threadIdx.x & 31;
    const int row = blockIdx.x * 8 + wid;
    const float maxn = 1.0f - 4e-3f;
    const float* mx = g_c + (size_t)row * DH;

    float mv[16], bv[16];
    const float4* m4 = reinterpret_cast<const float4*>(mx);
    const float4* b4 = reinterpret_cast<const float4*>(b1);
    #pragma unroll
    for (int i = 0; i < 4; i++) {
        float4 a = m4[lane * 4 + i];
        mv[4 * i] = a.x; mv[4 * i + 1] = a.y; mv[4 * i + 2] = a.z; mv[4 * i + 3] = a.w;
        float4 b = b4[lane * 4 + i];
        bv[4 * i] = b.x; bv[4 * i + 1] = b.y; bv[4 * i + 2] = b.z; bv[4 * i + 3] = b.w;
    }
    float pm = 0.f, pvb = 0.f, py = 0.f;
    #pragma unroll
    for (int i = 0; i < 16; i++) {
        pm  = fmaf(mv[i], mv[i], pm);
        pvb = fmaf(mv[i], bv[i], pvb);
        py  = fmaf(bv[i], bv[i], py);
    }
    float mxn2 = wred(pm), vb = wred(pvb), y2 = wred(py);

    float xn  = fmaxf(sqrtf(g_xn2[row]), 1e-15f);
    float mxn = fmaxf(sqrtf(mxn2), 1e-15f);
    float ns  = tanh_fast(mxn / xn * artanh_fast(xn));
    float s   = ns / mxn;
    float f1  = ns > maxn ? maxn / ns : 1.f;
    float sc1 = s * f1;
    float ncl = fminf(ns, maxn);
    float x2  = ncl * ncl;
    float xy  = sc1 * vb;
    float den = fmaxf(1.f + 2.f * xy + x2 * y2, 1e-15f);
    float chv = (1.f + 2.f * xy + y2) / den;
    float cb  = (1.f - x2) / den;
    float al  = chv * sc1, be = cb;
    float np2 = al * al * mxn2 + 2.f * al * be * vb + be * be * y2;
    float np  = fmaxf(sqrtf(np2), 1e-15f);
    float f2  = np > maxn ? maxn / np : 1.f;
    float nn  = fminf(np, maxn);
    float gg  = artanh_fast(nn) / nn * f2;

    float w[16], pw = 0.f;
    #pragma unroll
    for (int i = 0; i < 16; i++) {
        w[i] = tanh_fast(gg * fmaf(al, mv[i], be * bv[i]));
        pw = fmaf(w[i], w[i], pw);
    }
    float wn2 = wred(pw);
    float wn = fmaxf(sqrtf(wn2), 1e-15f);
    float tn = tanh_fast(wn);
    float hc = fminf(tn, maxn);
    float e3 = hc / wn;
    if (lane == 0) g_hn2[row] = hc * hc;

    uint32_t ph[8], pl[8];
    #pragma unroll
    for (int i = 0; i < 8; i++) {
        float v0 = e3 * w[2 * i], v1 = e3 * w[2 * i + 1];
        __nv_bfloat16 h0 = __float2bfloat16(v0), h1 = __float2bfloat16(v1);
        __nv_bfloat16 l0 = __float2bfloat16(v0 - __bfloat162float(h0));
        __nv_bfloat16 l1 = __float2bfloat16(v1 - __bfloat162float(h1));
        ph[i] = (uint32_t)__bfloat16_as_ushort(h0) | ((uint32_t)__bfloat16_as_ushort(h1) << 16);
        pl[i] = (uint32_t)__bfloat16_as_ushort(l0) | ((uint32_t)__bfloat16_as_ushort(l1) << 16);
    }
    uint4* dh = reinterpret_cast<uint4*>(g_hhi + (size_t)row * DH + lane * 16);
    uint4* dl = reinterpret_cast<uint4*>(g_hlo + (size_t)row * DH + lane * 16);
    dh[0] = make_uint4(ph[0], ph[1], ph[2], ph[3]);
    dh[1] = make_uint4(ph[4], ph[5], ph[6], ph[7]);
    dl[0] = make_uint4(pl[0], pl[1], pl[2], pl[3]);
    dl[1] = make_uint4(pl[4], pl[5], pl[6], pl[7]);
}

// ---------------- launch ----------------
extern "C" void kernel_launch(void* const* d_in, const int* in_sizes, int n_in,
                              void* d_out, int out_size) {
    const float* x  = (const float*)d_in[0];
    const float* W1 = (const float*)d_in[1];
    const float* b1 = (const float*)d_in[2];
    const float* W2 = (const float*)d_in[3];
    const float* b2 = (const float*)d_in[4];
    float* out = (float*)d_out;

    __nv_bfloat16 *xhi, *xlo, *w1hi, *w1lo, *w2hi, *w2lo, *hhi, *hlo;
    float* c;
    cudaGetSymbolAddress((void**)&xhi, g_xhi);
    cudaGetSymbolAddress((void**)&xlo, g_xlo);
    cudaGetSymbolAddress((void**)&w1hi, g_w1hi);
    cudaGetSymbolAddress((void**)&w1lo, g_w1lo);
    cudaGetSymbolAddress((void**)&w2hi, g_w2hi);
    cudaGetSymbolAddress((void**)&w2lo, g_w2lo);
    cudaGetSymbolAddress((void**)&hhi, g_hhi);
    cudaGetSymbolAddress((void**)&hlo, g_hlo);
    cudaGetSymbolAddress((void**)&c, g_c);

    cudaFuncSetAttribute(mma_gemm<DIN, DH>, cudaFuncAttributeMaxDynamicSharedMemorySize, GEMM_SMEM);
    cudaFuncSetAttribute(gemm2_fused, cudaFuncAttributeMaxDynamicSharedMemorySize, G2_SMEM);

    convert_x_kernel<<<BATCH / 8, 256>>>(x);
    convert_w_kernel<<<(DH * DIN + 255) / 256, 256>>>(W1, W2);

    // layer 1: mx1 = x @ W1^T  [B, 512]
    mma_gemm<DIN, DH><<<dim3(DH / 64, BATCH / 128), 256, GEMM_SMEM>>>(xhi, xlo, w1hi, w1lo, c);
    ew1_warp<<<BATCH / 8, 256>>>(b1);

    // layer 2 fused: out = ew2(h @ W2^T)  [B, 128]
    gemm2_fused<<<dim3(1, BATCH / 128), 256, G2_SMEM>>>(hhi, hlo, w2hi, w2lo, b2, out);
}